// round 7
// baseline (speedup 1.0000x reference)
#include <cuda_runtime.h>

#define N 2048
#define HID 128
#define HEADS 8
#define QT 64            // queries per attn block (2 per thread-lane)
#define KT 8             // keys per smem tile
#define SSPLIT 16        // KV splits
#define KS (N / SSPLIT)  // 128 keys per split
#define NT (KS / KT)     // 16 tiles
#define TILE_F (KT * HID)
#define LOG2E 1.4426950408889634f
#define SCALE 0.25f      // HEAD_DIM^-0.5

// ---------------- scratch (device globals) ----------------------------------
__device__ __align__(16) float g_q[N * HID];
__device__ __align__(16) float g_k[N * HID];
__device__ __align__(16) float g_v[N * HID];
__device__ __align__(16) float g_plh[N * HEADS * SSPLIT];        // [q][h][split]
__device__ __align__(16) float g_pacc[(size_t)N * SSPLIT * HID]; // [q][split][h*16+d]

// ---------------- packed fp32x2 + fast exp2 helpers -------------------------
union F2U { float2 f2; unsigned long long u; };

__device__ __forceinline__ float2 ffma2(float2 a, float2 b, float2 c) {
    F2U ua, ub, uc, ur;
    ua.f2 = a; ub.f2 = b; uc.f2 = c;
    asm("fma.rn.f32x2 %0, %1, %2, %3;" : "=l"(ur.u) : "l"(ua.u), "l"(ub.u), "l"(uc.u));
    return ur.f2;
}
__device__ __forceinline__ float2 fmul2(float2 a, float2 b) {
    F2U ua, ub, ur;
    ua.f2 = a; ub.f2 = b;
    asm("mul.rn.f32x2 %0, %1, %2;" : "=l"(ur.u) : "l"(ua.u), "l"(ub.u));
    return ur.f2;
}
__device__ __forceinline__ float ex2f(float x) {
    float y;
    asm("ex2.approx.f32 %0, %1;" : "=f"(y) : "f"(x));
    return y;
}
__device__ __forceinline__ float2 f2(float a, float b) { return make_float2(a, b); }

#define CP16(dst_u32, src_ptr) \
    asm volatile("cp.async.ca.shared.global [%0], [%1], 16;" :: "r"(dst_u32), "l"(src_ptr))
#define CPCOMMIT() asm volatile("cp.async.commit_group;")
#define CPWAIT1()  asm volatile("cp.async.wait_group 1;")

// ---------------- no-op spacers (keep attn as ncu's 4th launch) --------------
__global__ void spacer_kernel() {}

// ---------------- QKV projection (R2 structure — measured 13.1us) -----------
// grid (N/16, 3), 128 threads. q pre-scaled by SCALE*LOG2E.
__global__ void __launch_bounds__(128) proj_qkv_kernel(
    const float* __restrict__ x,
    const float* __restrict__ Wq, const float* __restrict__ bq,
    const float* __restrict__ Wk, const float* __restrict__ bk,
    const float* __restrict__ Wv, const float* __restrict__ bv)
{
    __shared__ float xs[16 * HID];     // 8 KB
    __shared__ float Wt[128 * 68];     // 34.8 KB, padded stride 68
    const int tid  = threadIdx.x;
    const int row0 = blockIdx.x * 16;
    const int which = blockIdx.y;
    const float* __restrict__ W = (which == 0) ? Wq : (which == 1) ? Wk : Wv;
    const float* __restrict__ b = (which == 0) ? bq : (which == 1) ? bk : bv;
    float* out = (which == 0) ? g_q : (which == 1) ? g_k : g_v;
    const float osc = (which == 0) ? (SCALE * LOG2E) : 1.0f;

    {   // stage x rows (coalesced)
        const float4* x4 = (const float4*)(x + (size_t)row0 * HID);
        #pragma unroll
        for (int i = 0; i < 4; i++)
            ((float4*)xs)[tid + 128 * i] = x4[tid + 128 * i];
    }

    float2 acc2[16];
    #pragma unroll
    for (int r = 0; r < 16; r++) acc2[r] = f2(0.f, 0.f);

    #pragma unroll
    for (int cj = 0; cj < 2; cj++) {
        __syncthreads();
        #pragma unroll
        for (int i = 0; i < 16; i++) {
            int fidx = tid + 128 * i;
            int c = fidx >> 4, jq = fidx & 15;
            *(float4*)(Wt + c * 68 + jq * 4) =
                *(const float4*)(W + (size_t)c * HID + cj * 64 + jq * 4);
        }
        __syncthreads();
        #pragma unroll
        for (int jq = 0; jq < 16; jq++) {
            float4 w = *(const float4*)(Wt + tid * 68 + jq * 4);
            float2 wxy = f2(w.x, w.y), wzw = f2(w.z, w.w);
            #pragma unroll
            for (int r = 0; r < 16; r++) {
                float4 xv = *(const float4*)(xs + r * HID + cj * 64 + jq * 4);
                acc2[r] = ffma2(wxy, f2(xv.x, xv.y), acc2[r]);
                acc2[r] = ffma2(wzw, f2(xv.z, xv.w), acc2[r]);
            }
        }
    }
    const float bb = b[tid];
    #pragma unroll
    for (int r = 0; r < 16; r++)
        out[(size_t)(row0 + r) * HID + tid] = (acc2[r].x + acc2[r].y + bb) * osc;
}

// ---------------- fused attention: 2 queries/thread -------------------------
// grid (N/QT, SSPLIT), 256 threads. warp = head, lane = queries (ql, ql+32).
// No-max softmax in log2 domain. KV: cp.async ring-3. Bias: reg prefetch 1
// tile ahead, transformed (b*LOG2E + pen) into stride-65 smem (reads CF).
// K/V broadcast LDS amortized over 2 queries -> L1 wavefronts/cell halved.
__global__ void __launch_bounds__(256, 2) attn_kernel(
    const float* __restrict__ bias, const unsigned char* __restrict__ mask)
{
    __shared__ float sKV[2][3][TILE_F];      // 24 KB
    __shared__ float sB[2][QT * 65];         // 33.3 KB
    __shared__ float sPen[KS];               // 0.5 KB

    const int tid = threadIdx.x;
    const int h   = tid >> 5;
    const int ql  = tid & 31;
    const int qb  = blockIdx.x * QT;
    const int q1  = qb + ql;
    const int q2  = q1 + 32;
    const int split = blockIdx.y;
    const int k0  = split * KS;

    if (tid < KS) sPen[tid] = mask[k0 + tid] ? -1e30f : 0.0f;

    const float* gK = g_k + (size_t)k0 * HID;
    const float* gV = g_v + (size_t)k0 * HID;
    const unsigned sKa = (unsigned)__cvta_generic_to_shared(&sKV[0][0][0]);
    const unsigned sVa = sKa + 3 * TILE_F * 4;

    // KV tiles 0,1 in flight (1024 floats per tile, 1 float4/thread)
    CP16(sKa + tid * 16, gK + tid * 4);
    CP16(sVa + tid * 16, gV + tid * 4);
    CPCOMMIT();
    CP16(sKa + TILE_F * 4 + tid * 16, gK + TILE_F + tid * 4);
    CP16(sVa + TILE_F * 4 + tid * 16, gV + TILE_F + tid * 4);
    CPCOMMIT();

    // bias prefetch: thread owns row qrow (0..63), cols kko*16..+15
    const int qrow = tid >> 2;
    const int kko  = tid & 3;
    const float* gbRow = bias + (size_t)(qb + qrow) * (N * HEADS)
                              + (size_t)k0 * HEADS + kko * 16;
    float4 bb0 = *(const float4*)(gbRow);
    float4 bb1 = *(const float4*)(gbRow + 4);
    float4 bb2 = *(const float4*)(gbRow + 8);
    float4 bb3 = *(const float4*)(gbRow + 12);

    // q vectors for both queries (packed along d)
    float2 qv1[8], qv2[8];
    {
        const float4* qp1 = (const float4*)(g_q + (size_t)q1 * HID + h * 16);
        const float4* qp2 = (const float4*)(g_q + (size_t)q2 * HID + h * 16);
        #pragma unroll
        for (int i = 0; i < 4; i++) {
            float4 a = qp1[i], c = qp2[i];
            qv1[2 * i]     = f2(a.x, a.y);  qv1[2 * i + 1] = f2(a.z, a.w);
            qv2[2 * i]     = f2(c.x, c.y);  qv2[2 * i + 1] = f2(c.z, c.w);
        }
    }

    float l1 = 0.f, l2 = 0.f;
    float2 a1[8], a2[8];
    #pragma unroll
    for (int i = 0; i < 8; i++) { a1[i] = f2(0.f, 0.f); a2[i] = f2(0.f, 0.f); }

    __syncthreads();   // sPen visible before first transform

    for (int t = 0; t < NT; t++) {
        // transform bias tile t: 16 floats = keys {2*kko, 2*kko+1}, 8 heads each
        {
            float penA = sPen[t * KT + kko * 2];
            float penB = sPen[t * KT + kko * 2 + 1];
            float* dst = &sB[t & 1][qrow * 65 + kko * 16];
            dst[0]  = fmaf(bb0.x, LOG2E, penA);
            dst[1]  = fmaf(bb0.y, LOG2E, penA);
            dst[2]  = fmaf(bb0.z, LOG2E, penA);
            dst[3]  = fmaf(bb0.w, LOG2E, penA);
            dst[4]  = fmaf(bb1.x, LOG2E, penA);
            dst[5]  = fmaf(bb1.y, LOG2E, penA);
            dst[6]  = fmaf(bb1.z, LOG2E, penA);
            dst[7]  = fmaf(bb1.w, LOG2E, penA);
            dst[8]  = fmaf(bb2.x, LOG2E, penB);
            dst[9]  = fmaf(bb2.y, LOG2E, penB);
            dst[10] = fmaf(bb2.z, LOG2E, penB);
            dst[11] = fmaf(bb2.w, LOG2E, penB);
            dst[12] = fmaf(bb3.x, LOG2E, penB);
            dst[13] = fmaf(bb3.y, LOG2E, penB);
            dst[14] = fmaf(bb3.z, LOG2E, penB);
            dst[15] = fmaf(bb3.w, LOG2E, penB);
        }
        // prefetch bias tile t+1 (KT*HEADS = 64 floats per tile per row)
        if (t + 1 < NT) {
            const float* nb = gbRow + (size_t)(t + 1) * (KT * HEADS);
            bb0 = *(const float4*)(nb);
            bb1 = *(const float4*)(nb + 4);
            bb2 = *(const float4*)(nb + 8);
            bb3 = *(const float4*)(nb + 12);
        }
        CPWAIT1();                 // KV tile t resident
        __syncthreads();           // publish sB tile + KV block-wide
        if (t + 2 < NT) {          // KV tile t+2 into ring (readers done)
            int bidx = (t + 2) % 3;
            CP16(sKa + (bidx * TILE_F + tid * 4) * 4, gK + (size_t)(t + 2) * TILE_F + tid * 4);
            CP16(sVa + (bidx * TILE_F + tid * 4) * 4, gV + (size_t)(t + 2) * TILE_F + tid * 4);
        }
        CPCOMMIT();

        const float* kbuf  = sKV[0][t % 3];
        const float* vbuf  = sKV[1][t % 3];
        const float* brow1 = &sB[t & 1][ql * 65 + h];
        const float* brow2 = brow1 + 32 * 65;
        #pragma unroll
        for (int kk = 0; kk < KT; kk++) {
            const float4* kp = (const float4*)(kbuf + kk * HID + h * 16);
            float4 u0 = kp[0], u1 = kp[1];
            float2 d0 = fmul2(qv1[0], f2(u0.x, u0.y));
            float2 e0 = fmul2(qv2[0], f2(u0.x, u0.y));
            d0 = ffma2(qv1[1], f2(u0.z, u0.w), d0);
            e0 = ffma2(qv2[1], f2(u0.z, u0.w), e0);
            d0 = ffma2(qv1[2], f2(u1.x, u1.y), d0);
            e0 = ffma2(qv2[2], f2(u1.x, u1.y), e0);
            d0 = ffma2(qv1[3], f2(u1.z, u1.w), d0);
            e0 = ffma2(qv2[3], f2(u1.z, u1.w), e0);
            float4 u2 = kp[2], u3 = kp[3];
            d0 = ffma2(qv1[4], f2(u2.x, u2.y), d0);
            e0 = ffma2(qv2[4], f2(u2.x, u2.y), e0);
            d0 = ffma2(qv1[5], f2(u2.z, u2.w), d0);
            e0 = ffma2(qv2[5], f2(u2.z, u2.w), e0);
            d0 = ffma2(qv1[6], f2(u3.x, u3.y), d0);
            e0 = ffma2(qv2[6], f2(u3.x, u3.y), e0);
            d0 = ffma2(qv1[7], f2(u3.z, u3.w), d0);
            e0 = ffma2(qv2[7], f2(u3.z, u3.w), e0);
            float s1 = (d0.x + d0.y) + brow1[kk * 8];
            float s2 = (e0.x + e0.y) + brow2[kk * 8];
            float p1 = ex2f(s1), p2 = ex2f(s2);
            l1 += p1; l2 += p2;
            float2 p11 = f2(p1, p1), p22 = f2(p2, p2);
            const float4* vp = (const float4*)(vbuf + kk * HID + h * 16);
            float4 v0 = vp[0], v1 = vp[1];
            a1[0] = ffma2(p11, f2(v0.x, v0.y), a1[0]);
            a2[0] = ffma2(p22, f2(v0.x, v0.y), a2[0]);
            a1[1] = ffma2(p11, f2(v0.z, v0.w), a1[1]);
            a2[1] = ffma2(p22, f2(v0.z, v0.w), a2[1]);
            a1[2] = ffma2(p11, f2(v1.x, v1.y), a1[2]);
            a2[2] = ffma2(p22, f2(v1.x, v1.y), a2[2]);
            a1[3] = ffma2(p11, f2(v1.z, v1.w), a1[3]);
            a2[3] = ffma2(p22, f2(v1.z, v1.w), a2[3]);
            float4 v2 = vp[2], v3 = vp[3];
            a1[4] = ffma2(p11, f2(v2.x, v2.y), a1[4]);
            a2[4] = ffma2(p22, f2(v2.x, v2.y), a2[4]);
            a1[5] = ffma2(p11, f2(v2.z, v2.w), a1[5]);
            a2[5] = ffma2(p22, f2(v2.z, v2.w), a2[5]);
            a1[6] = ffma2(p11, f2(v3.x, v3.y), a1[6]);
            a2[6] = ffma2(p22, f2(v3.x, v3.y), a2[6]);
            a1[7] = ffma2(p11, f2(v3.z, v3.w), a1[7]);
            a2[7] = ffma2(p22, f2(v3.z, v3.w), a2[7]);
        }
    }

    g_plh[(q1 * HEADS + h) * SSPLIT + split] = l1;
    g_plh[(q2 * HEADS + h) * SSPLIT + split] = l2;
    {
        const float4* s1p = (const float4*)a1;
        const float4* s2p = (const float4*)a2;
        float4* d1 = (float4*)(g_pacc + ((size_t)q1 * SSPLIT + split) * HID + h * 16);
        float4* d2 = (float4*)(g_pacc + ((size_t)q2 * SSPLIT + split) * HID + h * 16);
        #pragma unroll
        for (int i = 0; i < 4; i++) { d1[i] = s1p[i]; d2[i] = s2p[i]; }
    }
}

// ---------------- fused merge + output projection (R2 structure) ------------
__global__ void __launch_bounds__(128) oproj_kernel(
    const float* __restrict__ Wo, const float* __restrict__ bo,
    float* __restrict__ out)
{
    __shared__ __align__(16) float xs[16 * HID];
    __shared__ float Wt[128 * 68];
    const int tid  = threadIdx.x;
    const int row0 = blockIdx.x * 16;
    const int myh  = tid >> 4;

    #pragma unroll
    for (int r = 0; r < 16; r++) {
        const int q = row0 + r;
        float lsum = 0.f;
        const float4* lp = (const float4*)(g_plh + (q * HEADS + myh) * SSPLIT);
        #pragma unroll
        for (int i = 0; i < 4; i++) {
            float4 t = lp[i];
            lsum += (t.x + t.y) + (t.z + t.w);
        }
        float v = 0.f;
        const float* pa = g_pacc + (size_t)q * SSPLIT * HID + tid;
        #pragma unroll
        for (int s = 0; s < SSPLIT; s++) v += pa[s * HID];
        xs[r * HID + tid] = v / lsum;
    }

    float2 acc2[16];
    #pragma unroll
    for (int r = 0; r < 16; r++) acc2[r] = f2(0.f, 0.f);

    #pragma unroll
    for (int cj = 0; cj < 2; cj++) {
        __syncthreads();
        #pragma unroll
        for (int i = 0; i < 16; i++) {
            int fidx = tid + 128 * i;
            int c = fidx >> 4, jq = fidx & 15;
            *(float4*)(Wt + c * 68 + jq * 4) =
                *(const float4*)(Wo + (size_t)c * HID + cj * 64 + jq * 4);
        }
        __syncthreads();
        #pragma unroll
        for (int jq = 0; jq < 16; jq++) {
            float4 w = *(const float4*)(Wt + tid * 68 + jq * 4);
            float2 wxy = f2(w.x, w.y), wzw = f2(w.z, w.w);
            #pragma unroll
            for (int r = 0; r < 16; r++) {
                float4 xv = *(const float4*)(xs + r * HID + cj * 64 + jq * 4);
                acc2[r] = ffma2(wxy, f2(xv.x, xv.y), acc2[r]);
                acc2[r] = ffma2(wzw, f2(xv.z, xv.w), acc2[r]);
            }
        }
    }
    const float bb = bo[tid];
    #pragma unroll
    for (int r = 0; r < 16; r++)
        out[(size_t)(row0 + r) * HID + tid] = acc2[r].x + acc2[r].y + bb;
}

// ---------------- launcher ---------------------------------------------------
extern "C" void kernel_launch(void* const* d_in, const int* in_sizes, int n_in,
                              void* d_out, int out_size)
{
    const float* x    = (const float*)d_in[0];
    const float* bias = (const float*)d_in[1];
    const unsigned char* mask = (const unsigned char*)d_in[2];
    const float* Wq = (const float*)d_in[3];
    const float* bq = (const float*)d_in[4];
    const float* Wk = (const float*)d_in[5];
    const float* bk = (const float*)d_in[6];
    const float* Wv = (const float*)d_in[7];
    const float* bv = (const float*)d_in[8];
    const float* Wo = (const float*)d_in[9];
    const float* bo = (const float*)d_in[10];

    // spacers keep attn as the 4th launch (the one ncu captures)
    spacer_kernel<<<1, 32>>>();
    spacer_kernel<<<1, 32>>>();
    proj_qkv_kernel<<<dim3(N / 16, 3), 128>>>(x, Wq, bq, Wk, bk, Wv, bv);
    attn_kernel<<<dim3(N / QT, SSPLIT), 256>>>(bias, mask);
    oproj_kernel<<<N / 16, 128>>>(Wo, bo, (float*)d_out);
}